// round 8
// baseline (speedup 1.0000x reference)
#include <cuda_runtime.h>

#define BATCH 256
#define NROWS 256
#define MCOLS 256
#define DDIM  32
#define LOG2E 1.4426950408889634f
#define BIGF  (1e8f * LOG2E)       // boundary in scaled (D*log2e) domain

// ---- phase 2 (DP) ----
#define TPB    128                 // 4 dp warps, 2 rows per thread
#define NWARP  4
#define SLACK  12                  // startup ring cushion (columns)
#define PF     8                   // prefetch depth in iterations (PF/2 float4 regs)
#define ITERS  288                 // 287 rounded up to PF multiple
#define I2PAD  152                 // slab pairs per (b,w): 304 slabs >= ITERS+PF

// ---- phase 1 ----
#define P1_TPB 64                  // 2 warps; warp q covers dp-warp block w = 2*by + q
#define WIN    33                  // diagonal ring window (lane span 32 + 1)

// skewed dist scratch: [b][w][i2][lane] = (d_row0@i, d_row1@i, d_row0@i+1, d_row1@i+1)
// where rows = 64w + 2*lane (+1), col = i - lane; scaled by log2e.  ~80 MB.
__device__ float4 g_skew4[(size_t)BATCH * NWARP * I2PAD * 32];
__device__ float  g_part[BATCH];
__device__ int    g_count;

typedef unsigned long long u64;

#define FMA_F32X2(d, a, b) \
    asm("fma.rn.f32x2 %0, %1, %2, %0;" : "+l"(d) : "l"(a), "l"(b))
#define PACK_F32X2(out, lo, hi) \
    asm("mov.b64 %0, {%1, %2};" : "=l"(out) : "f"(lo), "f"(hi))
#define UNPACK_F32X2(lo, hi, in) \
    asm("mov.b64 {%0, %1}, %2;" : "=f"(lo), "=f"(hi) : "l"(in))

__device__ __forceinline__ float ex2f(float x) {
    float r; asm("ex2.approx.f32 %0, %1;" : "=f"(r) : "f"(x)); return r;
}
__device__ __forceinline__ float lg2f(float x) {
    float r; asm("lg2.approx.f32 %0, %1;" : "=f"(r) : "f"(x)); return r;
}

// softmin in scaled (D*log2e) domain
__device__ __forceinline__ float softmin3s(float a, float b, float c) {
    float mn = fminf(fminf(a, b), c);
    float s  = ex2f(mn - a) + ex2f(mn - b) + ex2f(mn - c);
    return mn - lg2f(s);
}

// ============================================================
// Phase 1: distances written directly in skewed DP order.
// CTA = (batch b, row-half by); 64 threads = 2 warps; warp q -> dp warp 2*by+q.
// Thread (q, lane l): rows 64*(2*by+q) + 2l, 2l+1 in registers; y broadcast.
// Diagonal SMEM ring (WIN slabs) turns per-column results into per-slab
// coalesced STG.128 flushes.
// ============================================================
__global__ __launch_bounds__(P1_TPB)
void dist_kernel(const float* __restrict__ X, const float* __restrict__ Y) {
    __shared__ ulonglong2 sy[8 * 257];           // y chunk-transposed, padded
    __shared__ float      syn[MCOLS];            // |y_j|^2
    __shared__ float2     sring[2][WIN][32];     // per-warp diagonal ring

    const int t    = threadIdx.x;
    const int lane = t & 31;
    const int q    = t >> 5;
    const int b    = blockIdx.x;
    const int by   = blockIdx.y;
    const int wg   = 2 * by + q;                 // dp warp block
    const float* xb = X + (size_t)b * NROWS * DDIM;
    const float* yb = Y + (size_t)b * MCOLS * DDIM;

    const ulonglong2* yb16 = (const ulonglong2*)yb;
    for (int k = t; k < MCOLS * 8; k += P1_TPB) {
        int j = k >> 3, c = k & 7;
        sy[c * 257 + j] = yb16[k];
    }
    for (int j = t; j < MCOLS; j += P1_TPB) {
        const float4* row = (const float4*)(yb + j * DDIM);
        float acc = 0.f;
        #pragma unroll
        for (int c = 0; c < 8; c++) {
            float4 v = row[c];
            acc += v.x * v.x + v.y * v.y + v.z * v.z + v.w * v.w;
        }
        syn[j] = acc;
    }

    // x row pair (64*wg + 2l, +1) in registers, packed f32x2
    u64 ax0[16], ax1[16];
    float xx0 = 0.f, xx1 = 0.f;
    {
        const float4* r0 = (const float4*)(xb + (size_t)(64 * wg + 2 * lane)     * DDIM);
        const float4* r1 = (const float4*)(xb + (size_t)(64 * wg + 2 * lane + 1) * DDIM);
        #pragma unroll
        for (int c = 0; c < 8; c++) {
            float4 v0 = r0[c], v1r = r1[c];
            PACK_F32X2(ax0[2*c],   v0.x,  v0.y);
            PACK_F32X2(ax0[2*c+1], v0.z,  v0.w);
            PACK_F32X2(ax1[2*c],   v1r.x, v1r.y);
            PACK_F32X2(ax1[2*c+1], v1r.z, v1r.w);
            xx0 += v0.x*v0.x + v0.y*v0.y + v0.z*v0.z + v0.w*v0.w;
            xx1 += v1r.x*v1r.x + v1r.y*v1r.y + v1r.z*v1r.z + v1r.w*v1r.w;
        }
    }
    __syncthreads();

    float4* dst = g_skew4 + ((size_t)(b * NWARP + wg) * I2PAD) * 32 + lane;

    int slot_w = lane % WIN;     // slot of slab (j + lane), starts at j=0
    int slot_f = 0;              // slot of slab j
    #pragma unroll 1
    for (int j = 0; j < ITERS; j++) {
        if (j < MCOLS) {
            // distances for rows (2l, 2l+1) at column j (y broadcast across warp)
            u64 a0 = 0ull, b0 = 0ull, a1 = 0ull, b1 = 0ull;
            #pragma unroll
            for (int c = 0; c < 8; c++) {
                ulonglong2 yv = sy[c * 257 + j];
                FMA_F32X2(a0, ax0[2*c],   yv.x);
                FMA_F32X2(b0, ax0[2*c+1], yv.y);
                FMA_F32X2(a1, ax1[2*c],   yv.x);
                FMA_F32X2(b1, ax1[2*c+1], yv.y);
            }
            float l0,h0,l0b,h0b,l1,h1,l1b,h1b;
            UNPACK_F32X2(l0,  h0,  a0);
            UNPACK_F32X2(l0b, h0b, b0);
            UNPACK_F32X2(l1,  h1,  a1);
            UNPACK_F32X2(l1b, h1b, b1);
            float dot0 = (l0 + h0) + (l0b + h0b);
            float dot1 = (l1 + h1) + (l1b + h1b);
            float yn = syn[j];
            float d0 = fmaxf(fmaf(-2.f, dot0, xx0 + yn), 0.f) * LOG2E;
            float d1 = fmaxf(fmaf(-2.f, dot1, xx1 + yn), 0.f) * LOG2E;
            sring[q][slot_w][lane] = make_float2(d0, d1);   // slab j+lane
        }
        __syncwarp();
        if (j & 1) {
            // flush completed slab pair (j-1, j) -> coalesced STG.128
            int s0 = slot_f - 1; if (s0 < 0) s0 += WIN;
            float2 pa = sring[q][s0][lane];
            float2 pb = sring[q][slot_f][lane];
            dst[(size_t)(j >> 1) * 32] = make_float4(pa.x, pa.y, pb.x, pb.y);
        }
        __syncwarp();
        if (++slot_w == WIN) slot_w = 0;
        if (++slot_f == WIN) slot_f = 0;
    }
}

// ============================================================
// Phase 2: DP over skewed dist; coalesced LDG.128 feeds 2 iterations.
// Self-timed warp ring (tagged SMEM words), softmin chain in registers.
// ============================================================
__global__ __launch_bounds__(TPB)
void dp_kernel(float* __restrict__ out) {
    __shared__ u64   ring[NWARP - 1][MCOLS];   // tagged (col+1 | value bits)
    __shared__ float red[TPB];
    __shared__ int   islast;

    const int t    = threadIdx.x;
    const int lane = t & 31;
    const int w    = t >> 5;
    const int b    = blockIdx.x;

    for (int k = t; k < (NWARP - 1) * MCOLS; k += TPB)
        ((u64*)ring)[k] = 0ull;                // tag 0 = not ready
    __syncthreads();

    const float4* db = g_skew4 + ((size_t)(b * NWARP + w) * I2PAD) * 32 + lane;

    float left0 = BIGF, left1 = BIGF;
    float tl = (t == 0) ? 0.f : BIGF;

    volatile u64* myring = (w < NWARP - 1) ? &ring[w][0]     : 0;
    volatile u64* upring = (w > 0)         ? &ring[w - 1][0] : 0;

    if (w > 0) {   // startup cushion
        u64 wd;
        do { wd = upring[SLACK]; } while ((unsigned)(wd >> 32) != (unsigned)(SLACK + 1));
    }

    // preload PF iterations (PF/2 float4)
    float4 q[PF / 2];
    #pragma unroll
    for (int k = 0; k < PF / 2; k++) q[k] = db[(size_t)k * 32];

    for (int i0 = 0; i0 < ITERS; i0 += PF) {
        #pragma unroll
        for (int k = 0; k < PF; k++) {
            const int i = i0 + k;
            float up_sh = __shfl_up_sync(0xffffffffu, left1, 1);
            const int ii = (i < MCOLS) ? i : (MCOLS - 1);

            u64 word = 0ull;
            if (w > 0) word = upring[ii];       // optimistic early read (broadcast)

            float4 qv = q[k >> 1];
            float dx = (k & 1) ? qv.z : qv.x;
            float dy = (k & 1) ? qv.w : qv.y;
            if (k & 1)                          // refill after both halves consumed
                q[k >> 1] = db[(size_t)((i + PF) >> 1) * 32];

            if (w > 0 && i < MCOLS) {           // tag check, rarely spins
                while ((unsigned)(word >> 32) != (unsigned)(ii + 1))
                    word = upring[ii];
            }
            float up0 = (lane == 0)
                      ? ((w == 0) ? BIGF : __uint_as_float((unsigned)word))
                      : up_sh;

            float v0  = dx + softmin3s(up0, left0, tl);
            float nv1 = dy + softmin3s(v0,  left1, left0);

            const int jj = i - lane;
            if (jj >= 0 && jj < MCOLS) {
                tl = up0; left0 = v0; left1 = nv1;
                if (lane == 31 && w < NWARP - 1)
                    myring[jj] = ((u64)(unsigned)(jj + 1) << 32) | (u64)__float_as_uint(nv1);
                if (w == NWARP - 1 && lane == 31 && jj == MCOLS - 1)
                    g_part[b] = nv1;            // scaled D[N][M]
            }
        }
    }

    // fused grid reduction (last CTA)
    __threadfence();
    __syncthreads();
    if (t == 0) islast = (atomicAdd(&g_count, 1) == BATCH - 1);
    __syncthreads();
    if (islast) {
        __threadfence();
        red[t] = g_part[t] + g_part[t + TPB];
        __syncthreads();
        #pragma unroll
        for (int off = TPB / 2; off > 0; off >>= 1) {
            if (t < off) red[t] += red[t + off];
            __syncthreads();
        }
        if (t == 0) {
            out[0] = red[0] * (1.0f / ((float)BATCH * LOG2E));
            g_count = 0;                        // reset for next graph replay
        }
    }
}

extern "C" void kernel_launch(void* const* d_in, const int* in_sizes, int n_in,
                              void* d_out, int out_size) {
    const float* x = (const float*)d_in[0];
    const float* y = (const float*)d_in[1];
    float* out = (float*)d_out;
    dist_kernel<<<dim3(BATCH, 2), P1_TPB>>>(x, y);
    dp_kernel<<<BATCH, TPB>>>(out);
}